// round 16
// baseline (speedup 1.0000x reference)
#include <cuda_runtime.h>
#include <cuda_fp16.h>
#include <cstdint>
#include <cstddef>

// ============================================================================
// Problem sizes
// ============================================================================
#define BATCH 4
#define SEQ   8192
#define DIM   1024
#define MTOT  (BATCH*SEQ)      // 32768 rows
#define NTOT  (2*DIM)          // 2048 combined output cols (gate | cand)
#define CH_T  32               // scan chunk length
#define NCHK  (SEQ/CH_T)       // 256 chunks per (b,d) channel
#define DV8   (DIM/8)          // 128 vec8 channel groups
#define CPL   (NCHK/32)        // 8 chunks per lane in pass2 warp scan

// ============================================================================
// Scratch (static device arrays — no allocation allowed)
// ============================================================================
__device__ __half g_xh[(size_t)MTOT*DIM];           // 64 MB
__device__ __half g_wh[(size_t)NTOT*DIM];           // 4 MB  (Wg rows 0..1023, Wc rows 1024..2047)
__device__ __half g_gate[(size_t)MTOT*DIM];         // 64 MB
__device__ __half g_cand[(size_t)MTOT*DIM];         // 64 MB
__device__ float g_Ast[(size_t)BATCH*NCHK*DIM];     // 4 MB
__device__ float g_Hst[(size_t)BATCH*NCHK*DIM];     // 4 MB
__device__ float g_Pst[(size_t)BATCH*NCHK*DIM];     // 4 MB

// ============================================================================
// Helpers (non-'a' PTX only: cp.async, ldmatrix, mma.sync)
// ============================================================================
__device__ __forceinline__ uint32_t smem_u32(const void* p){
    uint32_t a;
    asm("{ .reg .u64 t; cvta.to.shared.u64 t, %1; cvt.u32.u64 %0, t; }" : "=r"(a) : "l"(p));
    return a;
}
__device__ __forceinline__ void cp16(uint32_t smem_addr, const void* gptr){
    asm volatile("cp.async.cg.shared.global [%0], [%1], 16;"
                 :: "r"(smem_addr), "l"(__cvta_generic_to_global(gptr)) : "memory");
}
#define CP_COMMIT()  asm volatile("cp.async.commit_group;" ::: "memory")
#define CP_WAIT(n)   asm volatile("cp.async.wait_group %0;" :: "n"(n) : "memory")

__device__ __forceinline__ void ldsm4(uint32_t* r, uint32_t addr){
    asm volatile("ldmatrix.sync.aligned.m8n8.x4.shared.b16 {%0,%1,%2,%3}, [%4];"
                 : "=r"(r[0]),"=r"(r[1]),"=r"(r[2]),"=r"(r[3]) : "r"(addr));
}
__device__ __forceinline__ void mma16816(float* d, const uint32_t* a, const uint32_t* b){
    asm volatile("mma.sync.aligned.m16n8k16.row.col.f32.f16.f16.f32 "
                 "{%0,%1,%2,%3}, {%4,%5,%6,%7}, {%8,%9}, {%0,%1,%2,%3};"
                 : "+f"(d[0]),"+f"(d[1]),"+f"(d[2]),"+f"(d[3])
                 : "r"(a[0]),"r"(a[1]),"r"(a[2]),"r"(a[3]), "r"(b[0]),"r"(b[1]));
}

__device__ __forceinline__ float sigmoid_f(float v){
    return 1.0f / (1.0f + __expf(-v));
}
__device__ __forceinline__ float tanh_f(float v){
    float a = fabsf(v);
    float e = __expf(-2.0f * a);
    float t = (1.0f - e) / (1.0f + e);
    return copysignf(t, v);
}

// ============================================================================
// Kernel 1: fused convert — x (fp32->fp16) and [Wg;Wc] (fp32->fp16)
// ============================================================================
#define XCHUNKS ((size_t)MTOT*DIM/4)    // 8388608 float4 chunks of x

__global__ void conv_all_kernel(const float* __restrict__ x,
                                const float* __restrict__ Wg,
                                const float* __restrict__ Wc){
    size_t idx = (size_t)blockIdx.x * 256 + threadIdx.x;
    if (idx < XCHUNKS){
        size_t i = idx * 4;
        float4 v = *reinterpret_cast<const float4*>(x + i);
        __half2* ph = reinterpret_cast<__half2*>(g_xh + i);
        ph[0] = __floats2half2_rn(v.x, v.y);
        ph[1] = __floats2half2_rn(v.z, v.w);
    } else {
        size_t j = (idx - XCHUNKS) * 4;
        const size_t HALF = (size_t)DIM * DIM;
        float4 v = (j < HALF) ? *reinterpret_cast<const float4*>(Wg + j)
                              : *reinterpret_cast<const float4*>(Wc + (j - HALF));
        __half2* ph = reinterpret_cast<__half2*>(g_wh + j);
        ph[0] = __floats2half2_rn(v.x, v.y);
        ph[1] = __floats2half2_rn(v.z, v.w);
    }
}

// ============================================================================
// Kernel 2: fused dual GEMM (mma.sync fp16, fp32 accum)
//   BM=128, BN=128, BK=64 (SW128 rows), 8 warps, warp tile 64x32, 2 CTA/SM
//   PROVEN R13/R14 mainloop order (wait -> sync -> issue). Do not reorder.
// ============================================================================
#define BM 128
#define BN 128
#define BK 64
#define NSTAGE 3
#define KITER (DIM/BK)              // 16
#define ROWB 128                    // bytes per smem row (64 halves)
#define TILE_BYTES (128*ROWB)       // 16384 per matrix per stage
#define STAGE_BYTES (2*TILE_BYTES)  // A|B = 32768
#define GEMM_SMEM (NSTAGE*STAGE_BYTES + 128)
#define SWZ(off) ((off) ^ (((off) >> 3) & 0x70))

__global__ void __launch_bounds__(256, 2)
gemm_kernel(const float* __restrict__ bg, const float* __restrict__ bc){
    extern __shared__ char smem[];
    const uint32_t tb = (smem_u32(smem) + 127u) & ~127u;   // 128B-aligned tile base
    const int tid = threadIdx.x;
    const int wid = tid >> 5;
    const int lid = tid & 31;
    const int wm = wid >> 2;           // 0..1  (64-row slabs)
    const int wn = wid & 3;            // 0..3  (32-col slabs)
    const int n0 = blockIdx.x * BN;
    const int m0 = blockIdx.y * BM;

    // ---- thread-constant addressing ----
    const int tr  = tid >> 3;               // smem row 0..31 (+i*32)
    const int tc8 = (tid & 7) * 8;          // fp16 col of 16B chunk
    const uint32_t swzStore = SWZ((uint32_t)(tr * ROWB + tc8 * 2));
    const size_t baseA = (size_t)(m0 + tr) * DIM + tc8;
    const size_t baseB = (size_t)(n0 + tr) * DIM + tc8;

    // Fragment base offsets (unswizzled x has bits 5-6 clear, so the ks*32
    // advance is applied with XOR on the swizzled value).
    uint32_t offA[4], offB[2];
    #pragma unroll
    for (int mt = 0; mt < 4; mt++){
        int row = wm*64 + mt*16 + (lid & 15);
        offA[mt] = SWZ((uint32_t)(row * ROWB + ((lid >> 4) << 4)));
    }
    #pragma unroll
    for (int nt = 0; nt < 2; nt++){
        int row = wn*32 + nt*16 + (lid & 7) + ((lid >> 4) & 1) * 8;
        offB[nt] = SWZ((uint32_t)(row * ROWB + ((lid >> 3) & 1) * 16)) + TILE_BYTES;
    }

    auto load_stage = [&](int kk, int s){
        const uint32_t st = tb + (uint32_t)s * STAGE_BYTES + swzStore;
        const int k0 = kk * BK;
        #pragma unroll
        for (int i = 0; i < 4; i++)
            cp16(st + i*4096, g_xh + baseA + (size_t)(i*32)*DIM + k0);
        #pragma unroll
        for (int i = 0; i < 4; i++)
            cp16(st + TILE_BYTES + i*4096, g_wh + baseB + (size_t)(i*32)*DIM + k0);
        CP_COMMIT();
    };

    float acc[4][4][4];
    #pragma unroll
    for (int a = 0; a < 4; a++)
        #pragma unroll
        for (int b = 0; b < 4; b++)
            #pragma unroll
            for (int c = 0; c < 4; c++) acc[a][b][c] = 0.0f;

    #pragma unroll
    for (int s = 0; s < NSTAGE-1; s++) load_stage(s, s);

    for (int kk = 0; kk < KITER; kk++){
        CP_WAIT(NSTAGE-2);
        __syncthreads();

        if (kk + NSTAGE-1 < KITER) load_stage(kk + NSTAGE-1, (kk + NSTAGE-1) % NSTAGE);
        else CP_COMMIT();   // empty group keeps wait_group accounting exact

        const uint32_t st = tb + (uint32_t)(kk % NSTAGE) * STAGE_BYTES;

        #pragma unroll
        for (int ks = 0; ks < 4; ks++){         // four k16 steps per BK=64
            const uint32_t kx = (uint32_t)(ks * 32);
            uint32_t af[4][4], bf[2][4];
            #pragma unroll
            for (int mt = 0; mt < 4; mt++)
                ldsm4(af[mt], st + (offA[mt] ^ kx));
            #pragma unroll
            for (int nt = 0; nt < 2; nt++)
                ldsm4(bf[nt], st + (offB[nt] ^ kx));
            #pragma unroll
            for (int mt = 0; mt < 4; mt++){
                #pragma unroll
                for (int ng = 0; ng < 4; ng++){
                    mma16816(acc[mt][ng], af[mt], &bf[ng >> 1][(ng & 1) * 2]);
                }
            }
        }
    }

    // ---- epilogue: bias + activation, fp16 stores (half2)
    const bool isgate = (n0 < DIM);
    const float* bias = isgate ? bg : bc;
    __half* outp = isgate ? g_gate : g_cand;
    const int nb = isgate ? n0 : (n0 - DIM);
    const int g = lid >> 2, t = lid & 3;

    #pragma unroll
    for (int mt = 0; mt < 4; mt++){
        #pragma unroll
        for (int ng = 0; ng < 4; ng++){
            int col = nb + wn*32 + ng*8 + t*2;
            float b0 = bias[col], b1 = bias[col + 1];
            int row0 = m0 + wm*64 + mt*16 + g;
            int row1 = row0 + 8;
            float v00 = acc[mt][ng][0] + b0, v01 = acc[mt][ng][1] + b1;
            float v10 = acc[mt][ng][2] + b0, v11 = acc[mt][ng][3] + b1;
            if (isgate){
                v00 = sigmoid_f(v00); v01 = sigmoid_f(v01);
                v10 = sigmoid_f(v10); v11 = sigmoid_f(v11);
            } else {
                v00 = tanh_f(v00); v01 = tanh_f(v01);
                v10 = tanh_f(v10); v11 = tanh_f(v11);
            }
            *reinterpret_cast<__half2*>(outp + (size_t)row0 * DIM + col) = __floats2half2_rn(v00, v01);
            *reinterpret_cast<__half2*>(outp + (size_t)row1 * DIM + col) = __floats2half2_rn(v10, v11);
        }
    }
}

// ============================================================================
// Kernels 3/4/5: chunked linear-recurrence scan  h_t = g_t*h_{t-1} + c_t
// scan1/scan3: 8 channels/thread (16B fp16 loads) for MLP.
// ============================================================================
__device__ __forceinline__ void load8h(float* f, const __half* p){
    uint4 u = *reinterpret_cast<const uint4*>(p);
    __half2 h0 = *reinterpret_cast<__half2*>(&u.x);
    __half2 h1 = *reinterpret_cast<__half2*>(&u.y);
    __half2 h2 = *reinterpret_cast<__half2*>(&u.z);
    __half2 h3 = *reinterpret_cast<__half2*>(&u.w);
    float2 a = __half22float2(h0), b = __half22float2(h1);
    float2 c = __half22float2(h2), d = __half22float2(h3);
    f[0] = a.x; f[1] = a.y; f[2] = b.x; f[3] = b.y;
    f[4] = c.x; f[5] = c.y; f[6] = d.x; f[7] = d.y;
}

__global__ void scan_pass1(){
    int t = blockIdx.x * 256 + threadIdx.x;      // 131072 threads
    int d8 = t & (DV8 - 1);                      // vec8 channel group
    int ch = (t >> 7) & (NCHK - 1);
    int b  = t >> 15;
    size_t base = ((size_t)b * SEQ + (size_t)ch * CH_T) * DIM + (size_t)d8 * 8;
    float A[8] = {1.f,1.f,1.f,1.f,1.f,1.f,1.f,1.f};
    float H[8] = {0.f,0.f,0.f,0.f,0.f,0.f,0.f,0.f};
    #pragma unroll 4
    for (int i = 0; i < CH_T; i++){
        float g[8], c[8];
        load8h(g, g_gate + base);
        load8h(c, g_cand + base);
        #pragma unroll
        for (int j = 0; j < 8; j++){
            A[j] *= g[j];
            H[j] = g[j]*H[j] + c[j];
        }
        base += DIM;
    }
    size_t sidx = ((size_t)b * NCHK + ch) * DIM + (size_t)d8 * 8;
    *reinterpret_cast<float4*>(g_Ast + sidx)     = make_float4(A[0],A[1],A[2],A[3]);
    *reinterpret_cast<float4*>(g_Ast + sidx + 4) = make_float4(A[4],A[5],A[6],A[7]);
    *reinterpret_cast<float4*>(g_Hst + sidx)     = make_float4(H[0],H[1],H[2],H[3]);
    *reinterpret_cast<float4*>(g_Hst + sidx + 4) = make_float4(H[4],H[5],H[6],H[7]);
}

// ============================================================================
// Pass 2: chunk-prefix scan, smem-tiled for coalescing.
// Block = (b, 16-channel tile); 256 blocks total (> #SMs).
// ============================================================================
#define P2C 16
#define P2_PAD 17
#define P2_SMEM (2*NCHK*P2_PAD*4)    // 34816 bytes

__global__ void scan_pass2(){
    extern __shared__ float sm[];
    float* sA = sm;                   // [NCHK][17]
    float* sH = sm + NCHK*P2_PAD;     // [NCHK][17]
    const int b  = blockIdx.x >> 6;   // 64 d-tiles per batch
    const int d0 = (blockIdx.x & 63) * P2C;
    const int t = threadIdx.x;
    const int lane = t & 31;
    const int w = t >> 5;

    // coalesced tile load: each 16-thread group loads one 64B row segment
    {
        const int c = t & 15;
        const int r0 = t >> 4;        // 16 rows per sweep
        for (int rb = 0; rb < NCHK; rb += 16){
            int row = rb + r0;
            size_t g = ((size_t)b * NCHK + row) * DIM + d0 + c;
            sA[row*P2_PAD + c] = g_Ast[g];
            sH[row*P2_PAD + c] = g_Hst[g];
        }
    }
    __syncthreads();

    // each warp scans 2 channels; lane l owns chunks [l*CPL, (l+1)*CPL)
    for (int cc = 0; cc < 2; cc++){
        const int c = w*2 + cc;
        float Av[CPL], Hv[CPL];
        #pragma unroll
        for (int j = 0; j < CPL; j++){
            Av[j] = sA[(lane*CPL + j)*P2_PAD + c];
            Hv[j] = sH[(lane*CPL + j)*P2_PAD + c];
        }
        float a = 1.0f, h = 0.0f;
        #pragma unroll
        for (int j = 0; j < CPL; j++){ h = Av[j]*h + Hv[j]; a *= Av[j]; }
        #pragma unroll
        for (int off = 1; off < 32; off <<= 1){
            float ap = __shfl_up_sync(0xFFFFFFFFu, a, off);
            float hp = __shfl_up_sync(0xFFFFFFFFu, h, off);
            if (lane >= off){ h = a*hp + h; a *= ap; }
        }
        float he = __shfl_up_sync(0xFFFFFFFFu, h, 1);
        if (lane == 0) he = 0.0f;
        #pragma unroll
        for (int j = 0; j < CPL; j++){
            sA[(lane*CPL + j)*P2_PAD + c] = he;   // prefix entering chunk
            he = Av[j]*he + Hv[j];
        }
    }
    __syncthreads();

    // coalesced writeback of Pst tile
    {
        const int c = t & 15;
        const int r0 = t >> 4;
        for (int rb = 0; rb < NCHK; rb += 16){
            int row = rb + r0;
            size_t g = ((size_t)b * NCHK + row) * DIM + d0 + c;
            g_Pst[g] = sA[row*P2_PAD + c];
        }
    }
}

__global__ void scan_pass3(float* __restrict__ out){
    int t = blockIdx.x * 256 + threadIdx.x;      // 131072 threads
    int d8 = t & (DV8 - 1);
    int ch = (t >> 7) & (NCHK - 1);
    int b  = t >> 15;
    size_t base = ((size_t)b * SEQ + (size_t)ch * CH_T) * DIM + (size_t)d8 * 8;
    size_t sidx = ((size_t)b * NCHK + ch) * DIM + (size_t)d8 * 8;
    float4 p0 = *reinterpret_cast<const float4*>(g_Pst + sidx);
    float4 p1 = *reinterpret_cast<const float4*>(g_Pst + sidx + 4);
    float h[8] = {p0.x, p0.y, p0.z, p0.w, p1.x, p1.y, p1.z, p1.w};
    #pragma unroll 4
    for (int i = 0; i < CH_T; i++){
        float g[8], c[8];
        load8h(g, g_gate + base);
        load8h(c, g_cand + base);
        #pragma unroll
        for (int j = 0; j < 8; j++)
            h[j] = g[j]*h[j] + c[j];
        *reinterpret_cast<float4*>(out + base)     = make_float4(h[0],h[1],h[2],h[3]);
        *reinterpret_cast<float4*>(out + base + 4) = make_float4(h[4],h[5],h[6],h[7]);
        base += DIM;
    }
}

// ============================================================================
// Launch
// ============================================================================
extern "C" void kernel_launch(void* const* d_in, const int* in_sizes, int n_in,
                              void* d_out, int out_size){
    (void)in_sizes; (void)n_in; (void)out_size;
    const float* x  = (const float*)d_in[0];
    const float* Wg = (const float*)d_in[1];
    const float* bg = (const float*)d_in[2];
    const float* Wc = (const float*)d_in[3];
    const float* bc = (const float*)d_in[4];
    float* out = (float*)d_out;

    cudaFuncSetAttribute(gemm_kernel, cudaFuncAttributeMaxDynamicSharedMemorySize, GEMM_SMEM);
    cudaFuncSetAttribute(scan_pass2, cudaFuncAttributeMaxDynamicSharedMemorySize, P2_SMEM);

    const int conv_blocks = (int)(XCHUNKS/256 + (size_t)NTOT*DIM/4/256);   // 34816
    conv_all_kernel<<<conv_blocks, 256>>>(x, Wg, Wc);
    gemm_kernel<<<dim3(NTOT/BN, MTOT/BM), 256, GEMM_SMEM>>>(bg, bc);  // (16, 256)
    scan_pass1<<<(BATCH*NCHK*DV8)/256, 256>>>();                      // 512 blocks
    scan_pass2<<<BATCH*64, 256, P2_SMEM>>>();                         // 256 blocks, tiled
    scan_pass3<<<(BATCH*NCHK*DV8)/256, 256>>>(out);                   // 512 blocks
}

// round 17
// speedup vs baseline: 1.0457x; 1.0457x over previous
#include <cuda_runtime.h>
#include <cuda_fp16.h>
#include <cstdint>
#include <cstddef>

// ============================================================================
// Problem sizes
// ============================================================================
#define BATCH 4
#define SEQ   8192
#define DIM   1024
#define MTOT  (BATCH*SEQ)      // 32768 rows
#define CH_T  32               // scan chunk length
#define NCHK  (SEQ/CH_T)       // 256 chunks per (b,d) channel
#define DV8   (DIM/8)          // 128 vec8 channel groups
#define CPL   (NCHK/32)        // 8 chunks per lane in pass2 warp scan

// ============================================================================
// Scratch (static device arrays — no allocation allowed)
// ============================================================================
__device__ __half g_xh[(size_t)MTOT*DIM];           // 64 MB
__device__ __half g_wh[(size_t)2*DIM*DIM];          // 4 MB (Wg rows 0..1023, Wc rows 1024..2047)
__device__ __half g_gate[(size_t)MTOT*DIM];         // 64 MB
__device__ __half g_cand[(size_t)MTOT*DIM];         // 64 MB
__device__ float g_Ast[(size_t)BATCH*NCHK*DIM];     // 4 MB
__device__ float g_Hst[(size_t)BATCH*NCHK*DIM];     // 4 MB
__device__ float g_Pst[(size_t)BATCH*NCHK*DIM];     // 4 MB

// ============================================================================
// Helpers
// ============================================================================
__device__ __forceinline__ uint32_t smem_u32(const void* p){
    uint32_t a;
    asm("{ .reg .u64 t; cvta.to.shared.u64 t, %1; cvt.u32.u64 %0, t; }" : "=r"(a) : "l"(p));
    return a;
}
__device__ __forceinline__ void cp16(uint32_t smem_addr, const void* gptr){
    asm volatile("cp.async.cg.shared.global [%0], [%1], 16;"
                 :: "r"(smem_addr), "l"(__cvta_generic_to_global(gptr)) : "memory");
}
#define CP_COMMIT()  asm volatile("cp.async.commit_group;" ::: "memory")
#define CP_WAIT(n)   asm volatile("cp.async.wait_group %0;" :: "n"(n) : "memory")

__device__ __forceinline__ void ldsm4(uint32_t* r, uint32_t addr){
    asm volatile("ldmatrix.sync.aligned.m8n8.x4.shared.b16 {%0,%1,%2,%3}, [%4];"
                 : "=r"(r[0]),"=r"(r[1]),"=r"(r[2]),"=r"(r[3]) : "r"(addr));
}
__device__ __forceinline__ void mma16816(float* d, const uint32_t* a, const uint32_t* b){
    asm volatile("mma.sync.aligned.m16n8k16.row.col.f32.f16.f16.f32 "
                 "{%0,%1,%2,%3}, {%4,%5,%6,%7}, {%8,%9}, {%0,%1,%2,%3};"
                 : "+f"(d[0]),"+f"(d[1]),"+f"(d[2]),"+f"(d[3])
                 : "r"(a[0]),"r"(a[1]),"r"(a[2]),"r"(a[3]), "r"(b[0]),"r"(b[1]));
}

__device__ __forceinline__ float sigmoid_f(float v){
    return 1.0f / (1.0f + __expf(-v));
}
__device__ __forceinline__ float tanh_f(float v){
    float a = fabsf(v);
    float e = __expf(-2.0f * a);
    float t = (1.0f - e) / (1.0f + e);
    return copysignf(t, v);
}

// ============================================================================
// Kernel 1: fused convert — x (fp32->fp16) and [Wg;Wc] (fp32->fp16)
// ============================================================================
#define XCHUNKS ((size_t)MTOT*DIM/4)    // 8388608 float4 chunks of x

__global__ void conv_all_kernel(const float* __restrict__ x,
                                const float* __restrict__ Wg,
                                const float* __restrict__ Wc){
    size_t idx = (size_t)blockIdx.x * 256 + threadIdx.x;
    if (idx < XCHUNKS){
        size_t i = idx * 4;
        float4 v = *reinterpret_cast<const float4*>(x + i);
        __half2* ph = reinterpret_cast<__half2*>(g_xh + i);
        ph[0] = __floats2half2_rn(v.x, v.y);
        ph[1] = __floats2half2_rn(v.z, v.w);
    } else {
        size_t j = (idx - XCHUNKS) * 4;
        const size_t HALF = (size_t)DIM * DIM;
        float4 v = (j < HALF) ? *reinterpret_cast<const float4*>(Wg + j)
                              : *reinterpret_cast<const float4*>(Wc + (j - HALF));
        __half2* ph = reinterpret_cast<__half2*>(g_wh + j);
        ph[0] = __floats2half2_rn(v.x, v.y);
        ph[1] = __floats2half2_rn(v.z, v.w);
    }
}

// ============================================================================
// Kernel 2: fused dual GEMM + chunk-scan epilogue (replaces scan_pass1)
//   Each CTA: 128 m-rows x 128 d-cols, TWO K-loops (gate then cand) sharing
//   accumulators. Epilogue computes per-chunk (A,H) from smem-staged g/c.
//   Pipeline: NSTAGE=2, proven wait -> sync -> load order.
// ============================================================================
#define BM 128
#define BN 128
#define BK 64
#define KITER (DIM/BK)              // 16
#define ROWB 128                    // bytes per smem row (64 halves)
#define TILE_BYTES (128*ROWB)       // 16384 per matrix per stage
#define STAGE_BYTES (2*TILE_BYTES)  // A|B = 32768
#define GPAD 136                    // gbuf row stride in halves (conflict-free)
#define GBUF_BYTES (128*GPAD*2)     // 34816
#define GEMM_SMEM (128 + 2*STAGE_BYTES + GBUF_BYTES)   // 100480
#define SWZ(off) ((off) ^ (((off) >> 3) & 0x70))

__global__ void __launch_bounds__(256, 2)
gemm_kernel(const float* __restrict__ bg, const float* __restrict__ bc){
    extern __shared__ char smem[];
    char* tbp = (char*)(((uintptr_t)smem + 127) & ~(uintptr_t)127);
    const uint32_t tb = (smem_u32(smem) + 127u) & ~127u;
    __half* gbuf = reinterpret_cast<__half*>(tbp + 2*STAGE_BYTES);
    __half* cbuf = reinterpret_cast<__half*>(tbp);   // aliases stages (used last)

    const int tid = threadIdx.x;
    const int wid = tid >> 5;
    const int lid = tid & 31;
    const int wm = wid >> 2;           // 0..1  (64-row slabs)
    const int wn = wid & 3;            // 0..3  (32-col slabs)
    const int d0 = blockIdx.x * BN;    // 0..896 (d-columns)
    const int m0 = blockIdx.y * BM;

    // ---- thread-constant addressing ----
    const int tr  = tid >> 3;               // smem row 0..31 (+i*32)
    const int tc8 = (tid & 7) * 8;          // fp16 col of 16B chunk
    const uint32_t swzStore = SWZ((uint32_t)(tr * ROWB + tc8 * 2));
    const size_t baseA = (size_t)(m0 + tr) * DIM + tc8;
    const size_t baseW = (size_t)tr * DIM + tc8;     // within 128-row W slice

    uint32_t offA[4], offB[2];
    #pragma unroll
    for (int mt = 0; mt < 4; mt++){
        int row = wm*64 + mt*16 + (lid & 15);
        offA[mt] = SWZ((uint32_t)(row * ROWB + ((lid >> 4) << 4)));
    }
    #pragma unroll
    for (int nt = 0; nt < 2; nt++){
        int row = wn*32 + nt*16 + (lid & 7) + ((lid >> 4) & 1) * 8;
        offB[nt] = SWZ((uint32_t)(row * ROWB + ((lid >> 3) & 1) * 16)) + TILE_BYTES;
    }

    float acc[4][4][4];
    const int eg = lid >> 2, et = lid & 3;

    // ---- one GEMM sub-pass: W slice -> activation -> global + smem stage ----
    auto run_half = [&](const __half* wsrc, const float* bias, __half* outp,
                        __half* sbuf, bool isgate){
        #pragma unroll
        for (int a = 0; a < 4; a++)
            #pragma unroll
            for (int b = 0; b < 4; b++)
                #pragma unroll
                for (int c = 0; c < 4; c++) acc[a][b][c] = 0.0f;

        auto load_stage = [&](int kk, int s){
            const uint32_t st = tb + (uint32_t)s * STAGE_BYTES + swzStore;
            const int k0 = kk * BK;
            #pragma unroll
            for (int i = 0; i < 4; i++)
                cp16(st + i*4096, g_xh + baseA + (size_t)(i*32)*DIM + k0);
            #pragma unroll
            for (int i = 0; i < 4; i++)
                cp16(st + TILE_BYTES + i*4096, wsrc + baseW + (size_t)(i*32)*DIM + k0);
            CP_COMMIT();
        };

        load_stage(0, 0);
        for (int kk = 0; kk < KITER; kk++){
            CP_WAIT(0);
            __syncthreads();
            if (kk + 1 < KITER) load_stage(kk + 1, (kk + 1) & 1);
            else CP_COMMIT();

            const uint32_t st = tb + (uint32_t)(kk & 1) * STAGE_BYTES;
            #pragma unroll
            for (int ks = 0; ks < 4; ks++){
                const uint32_t kx = (uint32_t)(ks * 32);
                uint32_t af[4][4], bf[2][4];
                #pragma unroll
                for (int mt = 0; mt < 4; mt++)
                    ldsm4(af[mt], st + (offA[mt] ^ kx));
                #pragma unroll
                for (int nt = 0; nt < 2; nt++)
                    ldsm4(bf[nt], st + (offB[nt] ^ kx));
                #pragma unroll
                for (int mt = 0; mt < 4; mt++){
                    #pragma unroll
                    for (int ng = 0; ng < 4; ng++){
                        mma16816(acc[mt][ng], af[mt], &bf[ng >> 1][(ng & 1) * 2]);
                    }
                }
            }
        }

        // epilogue: bias + activation; store global fp16 AND smem stage buffer
        #pragma unroll
        for (int mt = 0; mt < 4; mt++){
            #pragma unroll
            for (int ng = 0; ng < 4; ng++){
                int col = wn*32 + ng*8 + et*2;          // local d col 0..127
                float b0 = bias[d0 + col], b1 = bias[d0 + col + 1];
                int r0 = wm*64 + mt*16 + eg;            // local rows
                int r1 = r0 + 8;
                float v00 = acc[mt][ng][0] + b0, v01 = acc[mt][ng][1] + b1;
                float v10 = acc[mt][ng][2] + b0, v11 = acc[mt][ng][3] + b1;
                if (isgate){
                    v00 = sigmoid_f(v00); v01 = sigmoid_f(v01);
                    v10 = sigmoid_f(v10); v11 = sigmoid_f(v11);
                } else {
                    v00 = tanh_f(v00); v01 = tanh_f(v01);
                    v10 = tanh_f(v10); v11 = tanh_f(v11);
                }
                __half2 h0 = __floats2half2_rn(v00, v01);
                __half2 h1 = __floats2half2_rn(v10, v11);
                *reinterpret_cast<__half2*>(outp + (size_t)(m0 + r0) * DIM + d0 + col) = h0;
                *reinterpret_cast<__half2*>(outp + (size_t)(m0 + r1) * DIM + d0 + col) = h1;
                *reinterpret_cast<__half2*>(sbuf + r0*GPAD + col) = h0;
                *reinterpret_cast<__half2*>(sbuf + r1*GPAD + col) = h1;
            }
        }
    };

    // Pass 1: gate (W rows d0..d0+127) -> gbuf (outside stage region, no alias)
    run_half(g_wh + (size_t)d0 * DIM, bg, g_gate, gbuf, true);
    // Pass 2: cand (W rows 1024+d0..). Sync before epilogue writes cbuf, which
    // aliases the pipeline stages (all stage reads complete after the loop).
    {
        const __half* wsrc = g_wh + (size_t)(DIM + d0) * DIM;
        // inline: loop identical to run_half but sync before epilogue store
        #pragma unroll
        for (int a = 0; a < 4; a++)
            #pragma unroll
            for (int b = 0; b < 4; b++)
                #pragma unroll
                for (int c = 0; c < 4; c++) acc[a][b][c] = 0.0f;

        auto load_stage = [&](int kk, int s){
            const uint32_t st = tb + (uint32_t)s * STAGE_BYTES + swzStore;
            const int k0 = kk * BK;
            #pragma unroll
            for (int i = 0; i < 4; i++)
                cp16(st + i*4096, g_xh + baseA + (size_t)(i*32)*DIM + k0);
            #pragma unroll
            for (int i = 0; i < 4; i++)
                cp16(st + TILE_BYTES + i*4096, wsrc + baseW + (size_t)(i*32)*DIM + k0);
            CP_COMMIT();
        };

        load_stage(0, 0);
        for (int kk = 0; kk < KITER; kk++){
            CP_WAIT(0);
            __syncthreads();
            if (kk + 1 < KITER) load_stage(kk + 1, (kk + 1) & 1);
            else CP_COMMIT();

            const uint32_t st = tb + (uint32_t)(kk & 1) * STAGE_BYTES;
            #pragma unroll
            for (int ks = 0; ks < 4; ks++){
                const uint32_t kx = (uint32_t)(ks * 32);
                uint32_t af[4][4], bf[2][4];
                #pragma unroll
                for (int mt = 0; mt < 4; mt++)
                    ldsm4(af[mt], st + (offA[mt] ^ kx));
                #pragma unroll
                for (int nt = 0; nt < 2; nt++)
                    ldsm4(bf[nt], st + (offB[nt] ^ kx));
                #pragma unroll
                for (int mt = 0; mt < 4; mt++){
                    #pragma unroll
                    for (int ng = 0; ng < 4; ng++){
                        mma16816(acc[mt][ng], af[mt], &bf[ng >> 1][(ng & 1) * 2]);
                    }
                }
            }
        }
        __syncthreads();   // all warps done reading stages -> cbuf alias safe

        #pragma unroll
        for (int mt = 0; mt < 4; mt++){
            #pragma unroll
            for (int ng = 0; ng < 4; ng++){
                int col = wn*32 + ng*8 + et*2;
                float b0 = bc[d0 + col], b1 = bc[d0 + col + 1];
                int r0 = wm*64 + mt*16 + eg;
                int r1 = r0 + 8;
                float v00 = tanh_f(acc[mt][ng][0] + b0), v01 = tanh_f(acc[mt][ng][1] + b1);
                float v10 = tanh_f(acc[mt][ng][2] + b0), v11 = tanh_f(acc[mt][ng][3] + b1);
                __half2 h0 = __floats2half2_rn(v00, v01);
                __half2 h1 = __floats2half2_rn(v10, v11);
                *reinterpret_cast<__half2*>(g_cand + (size_t)(m0 + r0) * DIM + d0 + col) = h0;
                *reinterpret_cast<__half2*>(g_cand + (size_t)(m0 + r1) * DIM + d0 + col) = h1;
                *reinterpret_cast<__half2*>(cbuf + r0*GPAD + col) = h0;
                *reinterpret_cast<__half2*>(cbuf + r1*GPAD + col) = h1;
            }
        }
    }
    __syncthreads();

    // ---- chunk-scan epilogue: 4 chunks x 128 d -> (A,H) per chunk ----
    const int b  = m0 >> 13;                 // m0 / SEQ
    const int c0 = (m0 & (SEQ - 1)) >> 5;    // first chunk index in this tile
    #pragma unroll
    for (int task = tid; task < 512; task += 256){
        int d   = task & 127;
        int chl = task >> 7;                 // 0..3
        float A = 1.0f, H = 0.0f;
        int rbase = chl * 32;
        #pragma unroll 8
        for (int i = 0; i < 32; i++){
            float g = __half2float(gbuf[(rbase + i)*GPAD + d]);
            float c = __half2float(cbuf[(rbase + i)*GPAD + d]);
            A *= g;
            H = g*H + c;
        }
        size_t sidx = ((size_t)b * NCHK + c0 + chl) * DIM + d0 + d;
        g_Ast[sidx] = A;
        g_Hst[sidx] = H;
    }
}

// ============================================================================
// Pass 2: chunk-prefix scan, smem-tiled (unchanged from R16)
// ============================================================================
#define P2C 16
#define P2_PAD 17
#define P2_SMEM (2*NCHK*P2_PAD*4)    // 34816 bytes

__global__ void scan_pass2(){
    extern __shared__ float sm[];
    float* sA = sm;                   // [NCHK][17]
    float* sH = sm + NCHK*P2_PAD;     // [NCHK][17]
    const int b  = blockIdx.x >> 6;
    const int d0 = (blockIdx.x & 63) * P2C;
    const int t = threadIdx.x;
    const int lane = t & 31;
    const int w = t >> 5;

    {
        const int c = t & 15;
        const int r0 = t >> 4;
        for (int rb = 0; rb < NCHK; rb += 16){
            int row = rb + r0;
            size_t g = ((size_t)b * NCHK + row) * DIM + d0 + c;
            sA[row*P2_PAD + c] = g_Ast[g];
            sH[row*P2_PAD + c] = g_Hst[g];
        }
    }
    __syncthreads();

    for (int cc = 0; cc < 2; cc++){
        const int c = w*2 + cc;
        float Av[CPL], Hv[CPL];
        #pragma unroll
        for (int j = 0; j < CPL; j++){
            Av[j] = sA[(lane*CPL + j)*P2_PAD + c];
            Hv[j] = sH[(lane*CPL + j)*P2_PAD + c];
        }
        float a = 1.0f, h = 0.0f;
        #pragma unroll
        for (int j = 0; j < CPL; j++){ h = Av[j]*h + Hv[j]; a *= Av[j]; }
        #pragma unroll
        for (int off = 1; off < 32; off <<= 1){
            float ap = __shfl_up_sync(0xFFFFFFFFu, a, off);
            float hp = __shfl_up_sync(0xFFFFFFFFu, h, off);
            if (lane >= off){ h = a*hp + h; a *= ap; }
        }
        float he = __shfl_up_sync(0xFFFFFFFFu, h, 1);
        if (lane == 0) he = 0.0f;
        #pragma unroll
        for (int j = 0; j < CPL; j++){
            sA[(lane*CPL + j)*P2_PAD + c] = he;
            he = Av[j]*he + Hv[j];
        }
    }
    __syncthreads();

    {
        const int c = t & 15;
        const int r0 = t >> 4;
        for (int rb = 0; rb < NCHK; rb += 16){
            int row = rb + r0;
            size_t g = ((size_t)b * NCHK + row) * DIM + d0 + c;
            g_Pst[g] = sA[row*P2_PAD + c];
        }
    }
}

// ============================================================================
// Pass 3: apply prefixes, write output (unchanged from R16, vec8)
// ============================================================================
__device__ __forceinline__ void load8h(float* f, const __half* p){
    uint4 u = *reinterpret_cast<const uint4*>(p);
    __half2 h0 = *reinterpret_cast<__half2*>(&u.x);
    __half2 h1 = *reinterpret_cast<__half2*>(&u.y);
    __half2 h2 = *reinterpret_cast<__half2*>(&u.z);
    __half2 h3 = *reinterpret_cast<__half2*>(&u.w);
    float2 a = __half22float2(h0), b = __half22float2(h1);
    float2 c = __half22float2(h2), d = __half22float2(h3);
    f[0] = a.x; f[1] = a.y; f[2] = b.x; f[3] = b.y;
    f[4] = c.x; f[5] = c.y; f[6] = d.x; f[7] = d.y;
}

__global__ void scan_pass3(float* __restrict__ out){
    int t = blockIdx.x * 256 + threadIdx.x;      // 131072 threads
    int d8 = t & (DV8 - 1);
    int ch = (t >> 7) & (NCHK - 1);
    int b  = t >> 15;
    size_t base = ((size_t)b * SEQ + (size_t)ch * CH_T) * DIM + (size_t)d8 * 8;
    size_t sidx = ((size_t)b * NCHK + ch) * DIM + (size_t)d8 * 8;
    float4 p0 = *reinterpret_cast<const float4*>(g_Pst + sidx);
    float4 p1 = *reinterpret_cast<const float4*>(g_Pst + sidx + 4);
    float h[8] = {p0.x, p0.y, p0.z, p0.w, p1.x, p1.y, p1.z, p1.w};
    #pragma unroll 4
    for (int i = 0; i < CH_T; i++){
        float g[8], c[8];
        load8h(g, g_gate + base);
        load8h(c, g_cand + base);
        #pragma unroll
        for (int j = 0; j < 8; j++)
            h[j] = g[j]*h[j] + c[j];
        *reinterpret_cast<float4*>(out + base)     = make_float4(h[0],h[1],h[2],h[3]);
        *reinterpret_cast<float4*>(out + base + 4) = make_float4(h[4],h[5],h[6],h[7]);
        base += DIM;
    }
}

// ============================================================================
// Launch
// ============================================================================
extern "C" void kernel_launch(void* const* d_in, const int* in_sizes, int n_in,
                              void* d_out, int out_size){
    (void)in_sizes; (void)n_in; (void)out_size;
    const float* x  = (const float*)d_in[0];
    const float* Wg = (const float*)d_in[1];
    const float* bg = (const float*)d_in[2];
    const float* Wc = (const float*)d_in[3];
    const float* bc = (const float*)d_in[4];
    float* out = (float*)d_out;

    cudaFuncSetAttribute(gemm_kernel, cudaFuncAttributeMaxDynamicSharedMemorySize, GEMM_SMEM);
    cudaFuncSetAttribute(scan_pass2, cudaFuncAttributeMaxDynamicSharedMemorySize, P2_SMEM);

    const int conv_blocks = (int)(XCHUNKS/256 + (size_t)2*DIM*DIM/4/256);   // 34816
    conv_all_kernel<<<conv_blocks, 256>>>(x, Wg, Wc);
    gemm_kernel<<<dim3(DIM/BN, MTOT/BM), 256, GEMM_SMEM>>>(bg, bc);   // (8, 256)
    scan_pass2<<<BATCH*64, 256, P2_SMEM>>>();                         // 256 blocks
    scan_pass3<<<(BATCH*NCHK*DV8)/256, 256>>>(out);                   // 512 blocks
}